// round 14
// baseline (speedup 1.0000x reference)
#include <cuda_runtime.h>
#include <cuda_bf16.h>
#include <math.h>
#include <stdint.h>

// Problem dims (fixed by the bench)
#define BB 131072
#define DD 256
#define KK 1024
#define LL 526

// -------- device scratch (no allocations allowed) --------
__device__ int   g_assign[BB];
__device__ int   g_count[KK];
__device__ int   g_offset[KK];
__device__ int   g_cursor[KK];
__device__ int   g_order[BB];
__device__ float g_c2[KK];
__device__ __align__(16) __nv_bfloat16 g_cbf[KK * 512];   // [k][hi 256 | lo 256]

// ============================================================
// helpers
// ============================================================
__device__ __forceinline__ uint32_t smem_u32(const void* p) {
    uint32_t a;
    asm("{ .reg .u64 t; cvta.to.shared.u64 t, %1; cvt.u32.u64 %0, t; }" : "=r"(a) : "l"(p));
    return a;
}
__device__ __forceinline__ void ldsm4(uint32_t* r, uint32_t addr) {
    asm volatile("ldmatrix.sync.aligned.m8n8.x4.shared.b16 {%0,%1,%2,%3}, [%4];"
                 : "=r"(r[0]), "=r"(r[1]), "=r"(r[2]), "=r"(r[3]) : "r"(addr));
}
__device__ __forceinline__ void mma16816(float* c, const uint32_t* a, const uint32_t* b) {
    asm volatile("mma.sync.aligned.m16n8k16.row.col.f32.bf16.bf16.f32 "
                 "{%0,%1,%2,%3}, {%4,%5,%6,%7}, {%8,%9}, {%0,%1,%2,%3};"
                 : "+f"(c[0]), "+f"(c[1]), "+f"(c[2]), "+f"(c[3])
                 : "r"(a[0]), "r"(a[1]), "r"(a[2]), "r"(a[3]), "r"(b[0]), "r"(b[1]));
}
__device__ __forceinline__ void sts64(uint32_t addr, uint32_t a, uint32_t b) {
    asm volatile("st.shared.v2.b32 [%0], {%1,%2};" :: "r"(addr), "r"(a), "r"(b) : "memory");
}
__device__ __forceinline__ void sts128(uint32_t addr, uint4 v) {
    asm volatile("st.shared.v4.b32 [%0], {%1,%2,%3,%4};"
                 :: "r"(addr), "r"(v.x), "r"(v.y), "r"(v.z), "r"(v.w) : "memory");
}
__device__ __forceinline__ void sts32(uint32_t addr, uint32_t v) {
    asm volatile("st.shared.b32 [%0], %1;" :: "r"(addr), "r"(v) : "memory");
}
__device__ __forceinline__ float lds_f(uint32_t addr) {
    float v; asm volatile("ld.shared.f32 %0, [%1];" : "=f"(v) : "r"(addr)); return v;
}
__device__ __forceinline__ void lds64(uint32_t addr, uint32_t& a, uint32_t& b) {
    asm volatile("ld.shared.v2.b32 {%0,%1}, [%2];" : "=r"(a), "=r"(b) : "r"(addr));
}
__device__ __forceinline__ uint32_t pack_bf2(float a, float b) {
    __nv_bfloat162 h = __floats2bfloat162_rn(a, b);   // .x = a (low 16 bits)
    return *(uint32_t*)&h;
}

// ============================================================
// K1: centroid norms (fp32) + bf16 hi/lo split table
// ============================================================
__global__ void c2bf_kernel(const float* __restrict__ cent) {
    int k    = blockIdx.x * 8 + (threadIdx.x >> 5);
    int lane = threadIdx.x & 31;
    const float4* row = (const float4*)(cent + (size_t)k * DD);
    __nv_bfloat16* hi = g_cbf + (size_t)k * 512;
    __nv_bfloat16* lo = hi + 256;
    float s = 0.f;
    #pragma unroll
    for (int i = 0; i < 2; ++i) {
        int f4 = lane + 32 * i;
        float4 v = row[f4];
        s = fmaf(v.x, v.x, s); s = fmaf(v.y, v.y, s);
        s = fmaf(v.z, v.z, s); s = fmaf(v.w, v.w, s);
        int d = f4 * 4;
        __nv_bfloat16 h0 = __float2bfloat16(v.x), h1 = __float2bfloat16(v.y);
        __nv_bfloat16 h2 = __float2bfloat16(v.z), h3 = __float2bfloat16(v.w);
        hi[d] = h0; hi[d+1] = h1; hi[d+2] = h2; hi[d+3] = h3;
        lo[d]   = __float2bfloat16(v.x - __bfloat162float(h0));
        lo[d+1] = __float2bfloat16(v.y - __bfloat162float(h1));
        lo[d+2] = __float2bfloat16(v.z - __bfloat162float(h2));
        lo[d+3] = __float2bfloat16(v.w - __bfloat162float(h3));
    }
    #pragma unroll
    for (int o = 16; o; o >>= 1) s += __shfl_xor_sync(0xffffffffu, s, o);
    if (!lane) g_c2[k] = s;
}

// ============================================================
// K2: bf16 hi/lo mma.sync distance GEMM + argmin
//   CTA = 128 points. A[128][512] bf16 swizzled K-major rows (1024B stride).
//   16 N-tiles of 64 centroids. Warps: 4 (m) x 2 (n), warp tile m32 x n32.
//   Per k16-step: 8 ldmatrix.x4 + 24 mma (hi*hi, hi*lo, lo*hi).
// ============================================================
#define A_OFF   0
#define A_BYTES (128 * 1024)
#define B_OFF   A_BYTES
#define B_BYTES (64 * 1024)
#define SC2_OFF (B_OFF + B_BYTES)          // 64 floats
#define X2_OFF  (SC2_OFF + 256)            // 128 floats
#define RED_OFF (X2_OFF + 512)             // 128 rows x 2 slots x 8B
#define SMEM_REQ (RED_OFF + 2048)

__global__ void __launch_bounds__(256, 1)
assign_kernel(const float* __restrict__ pts,
              float* __restrict__ o_assign, float* __restrict__ o_dist,
              float* __restrict__ o_disp) {
    extern __shared__ char smraw[];
    const uint32_t smb = smem_u32(smraw);
    const uint32_t smA = smb + A_OFF;
    const uint32_t smB = smb + B_OFF;
    const uint32_t smC2 = smb + SC2_OFF;
    const uint32_t smX2 = smb + X2_OFF;
    const uint32_t smRD = smb + RED_OFF;

    const int t    = threadIdx.x;
    const int wid  = t >> 5;
    const int lane = t & 31;
    const int blk  = blockIdx.x;

    // ---- A fill: fp32 -> bf16 hi/lo, swizzled; also x2 per point ----
    {
        const float4* src = (const float4*)(pts + (size_t)blk * 128 * DD);
        #pragma unroll
        for (int it = 0; it < 16; ++it) {
            int r = it * 8 + wid;
            uint32_t rowb = smA + r * 1024;
            uint32_t x = (uint32_t)((r & 7) << 4);
            float x2 = 0.f;
            #pragma unroll
            for (int h = 0; h < 2; ++h) {
                int f4 = h * 32 + lane;
                float4 v = src[r * 64 + f4];
                x2 = fmaf(v.x, v.x, x2); x2 = fmaf(v.y, v.y, x2);
                x2 = fmaf(v.z, v.z, x2); x2 = fmaf(v.w, v.w, x2);
                __nv_bfloat16 h0 = __float2bfloat16(v.x), h1 = __float2bfloat16(v.y);
                __nv_bfloat16 h2 = __float2bfloat16(v.z), h3 = __float2bfloat16(v.w);
                uint32_t hiA, hiB;
                { __nv_bfloat162 p(h0, h1); hiA = *(uint32_t*)&p; }
                { __nv_bfloat162 p(h2, h3); hiB = *(uint32_t*)&p; }
                uint32_t loA = pack_bf2(v.x - __bfloat162float(h0),
                                        v.y - __bfloat162float(h1));
                uint32_t loB = pack_bf2(v.z - __bfloat162float(h2),
                                        v.w - __bfloat162float(h3));
                uint32_t kb = (uint32_t)(f4 * 8);            // hi byte offset
                sts64(rowb + (kb ^ x), hiA, hiB);
                sts64(rowb + ((512 + kb) ^ x), loA, loB);
            }
            #pragma unroll
            for (int o = 16; o; o >>= 1) x2 += __shfl_xor_sync(0xffffffffu, x2, o);
            if (!lane) sts32(smX2 + r * 4, __float_as_uint(x2));
        }
    }

    // warp tiling: 4 m-groups x 2 n-groups
    const int wm = wid & 3;            // m0 = wm*32
    const int wn = wid >> 2;           // n0 = wn*32
    const int m0 = wm * 32;
    const int n0 = wn * 32;

    // ldmatrix lane addressing (loop-invariant parts)
    const int ar  = m0 + (lane & 15);
    const uint32_t aAdr = smA + ar * 1024;
    const uint32_t ax   = (uint32_t)((ar & 7) << 4);
    const uint32_t acA  = (uint32_t)((lane >> 4) << 4);
    const int br  = n0 + ((lane & 7) + ((lane >> 4) << 3));
    const uint32_t bAdr = smB + br * 1024;
    const uint32_t bx   = (uint32_t)((br & 7) << 4);
    const uint32_t bcA  = (uint32_t)(((lane >> 3) & 1) << 4);

    float acc[2][4][4];
    #pragma unroll
    for (int i = 0; i < 2; ++i)
        #pragma unroll
        for (int j = 0; j < 4; ++j)
            #pragma unroll
            for (int e = 0; e < 4; ++e) acc[i][j][e] = 0.f;

    float minv[2][2];
    int   mini[2][2];
    #pragma unroll
    for (int i = 0; i < 2; ++i)
        #pragma unroll
        for (int j = 0; j < 2; ++j) { minv[i][j] = 3.4e38f; mini[i][j] = 0; }

    for (int tile = 0; tile < 16; ++tile) {
        __syncthreads();   // epilogue of prev tile done before overwriting B/sc2
        // ---- B fill: 64 centroids x 1024B from g_cbf (hi|lo contiguous) ----
        {
            const uint4* src = (const uint4*)g_cbf + (size_t)(tile * 64) * 64;
            #pragma unroll
            for (int i = 0; i < 16; ++i) {
                int idx = i * 256 + t;
                int n  = idx >> 6;
                int ch = idx & 63;
                uint4 v = src[idx];
                sts128(smB + n * 1024 + (((uint32_t)(ch * 16)) ^ ((n & 7) << 4)), v);
            }
            if (t < 64) sts32(smC2 + t * 4, __float_as_uint(g_c2[tile * 64 + t]));
        }
        __syncthreads();

        // ---- mainloop: 16 k-steps of 16 ----
        #pragma unroll 2
        for (int ks = 0; ks < 16; ++ks) {
            uint32_t khb = (uint32_t)(ks * 32);
            uint32_t ah[2][4], al[2][4], bh[2][4], bl[2][4];
            ldsm4(ah[0], aAdr +         ((khb + acA) ^ ax));
            ldsm4(ah[1], aAdr + 16384 + ((khb + acA) ^ ax));
            ldsm4(al[0], aAdr +         ((512 + khb + acA) ^ ax));
            ldsm4(al[1], aAdr + 16384 + ((512 + khb + acA) ^ ax));
            ldsm4(bh[0], bAdr +         ((khb + bcA) ^ bx));
            ldsm4(bh[1], bAdr + 16384 + ((khb + bcA) ^ bx));
            ldsm4(bl[0], bAdr +         ((512 + khb + bcA) ^ bx));
            ldsm4(bl[1], bAdr + 16384 + ((512 + khb + bcA) ^ bx));
            // hi*hi
            #pragma unroll
            for (int mf = 0; mf < 2; ++mf)
                #pragma unroll
                for (int nf = 0; nf < 4; ++nf)
                    mma16816(acc[mf][nf], ah[mf], &bh[nf >> 1][(nf & 1) * 2]);
            // hi_a * lo_b
            #pragma unroll
            for (int mf = 0; mf < 2; ++mf)
                #pragma unroll
                for (int nf = 0; nf < 4; ++nf)
                    mma16816(acc[mf][nf], ah[mf], &bl[nf >> 1][(nf & 1) * 2]);
            // lo_a * hi_b
            #pragma unroll
            for (int mf = 0; mf < 2; ++mf)
                #pragma unroll
                for (int nf = 0; nf < 4; ++nf)
                    mma16816(acc[mf][nf], al[mf], &bh[nf >> 1][(nf & 1) * 2]);
        }

        // ---- epilogue: scores = c2 - 2*dot, running argmin; reset acc ----
        #pragma unroll
        for (int mf = 0; mf < 2; ++mf)
            #pragma unroll
            for (int nf = 0; nf < 4; ++nf) {
                int colb = n0 + nf * 8 + (lane & 3) * 2;   // within tile (0..63)
                float c20 = lds_f(smC2 + colb * 4);
                float c21 = lds_f(smC2 + colb * 4 + 4);
                int g0 = tile * 64 + colb;
                float* c = acc[mf][nf];
                float v0 = c20 - 2.f * c[0];
                float v1 = c21 - 2.f * c[1];
                float v2 = c20 - 2.f * c[2];
                float v3 = c21 - 2.f * c[3];
                if (v0 < minv[mf][0] || (v0 == minv[mf][0] && g0     < mini[mf][0])) { minv[mf][0] = v0; mini[mf][0] = g0; }
                if (v1 < minv[mf][0] || (v1 == minv[mf][0] && g0 + 1 < mini[mf][0])) { minv[mf][0] = v1; mini[mf][0] = g0 + 1; }
                if (v2 < minv[mf][1] || (v2 == minv[mf][1] && g0     < mini[mf][1])) { minv[mf][1] = v2; mini[mf][1] = g0; }
                if (v3 < minv[mf][1] || (v3 == minv[mf][1] && g0 + 1 < mini[mf][1])) { minv[mf][1] = v3; mini[mf][1] = g0 + 1; }
                c[0] = 0.f; c[1] = 0.f; c[2] = 0.f; c[3] = 0.f;
            }
    }

    // ---- reduce argmin: intra-warp over lane&3, then cross n-warp via smem ----
    #pragma unroll
    for (int off = 1; off < 4; off <<= 1) {
        #pragma unroll
        for (int mf = 0; mf < 2; ++mf)
            #pragma unroll
            for (int rh = 0; rh < 2; ++rh) {
                float ov = __shfl_xor_sync(0xffffffffu, minv[mf][rh], off);
                int   oi = __shfl_xor_sync(0xffffffffu, mini[mf][rh], off);
                if (ov < minv[mf][rh] || (ov == minv[mf][rh] && oi < mini[mf][rh])) {
                    minv[mf][rh] = ov; mini[mf][rh] = oi;
                }
            }
    }
    if ((lane & 3) == 0) {
        #pragma unroll
        for (int mf = 0; mf < 2; ++mf)
            #pragma unroll
            for (int rh = 0; rh < 2; ++rh) {
                int row = m0 + mf * 16 + rh * 8 + (lane >> 2);
                sts64(smRD + (row * 2 + wn) * 8,
                      __float_as_uint(minv[mf][rh]), (uint32_t)mini[mf][rh]);
            }
    }
    __syncthreads();

    if (t < 128) {
        uint32_t v0u, i0u, v1u, i1u;
        lds64(smRD + (t * 2 + 0) * 8, v0u, i0u);
        lds64(smRD + (t * 2 + 1) * 8, v1u, i1u);
        float v0 = __uint_as_float(v0u), v1 = __uint_as_float(v1u);
        int   i0 = (int)i0u,             i1 = (int)i1u;
        float bv = v0; int bi = i0;
        if (v1 < bv || (v1 == bv && i1 < bi)) { bv = v1; bi = i1; }

        int p = blk * 128 + t;
        o_assign[p] = (float)bi;
        g_assign[p] = bi;
        float dist = bv + lds_f(smX2 + t * 4);
        o_dist[p] = dist;
        atomicAdd(&o_disp[bi], dist);
        atomicAdd(&g_count[bi], 1);
    }
}

// ============================================================
// K3: exclusive scan of cluster counts (single block) + new_n output
// ============================================================
__global__ void scan_kernel(float* __restrict__ o_nn) {
    __shared__ int sc[KK];
    int t = threadIdx.x;
    int v = g_count[t];
    o_nn[t] = (float)v;
    sc[t] = v;
    __syncthreads();
    for (int o = 1; o < KK; o <<= 1) {
        int add = (t >= o) ? sc[t - o] : 0;
        __syncthreads();
        sc[t] += add;
        __syncthreads();
    }
    int excl = sc[t] - v;
    g_offset[t] = excl;
    g_cursor[t] = excl;
}

// ============================================================
// K4: per-point labels cosine + dispersion_labels + bucket scatter
// ============================================================
__global__ void __launch_bounds__(256)
label_kernel(const float* __restrict__ labels, const float* __restrict__ rl,
             float* __restrict__ o_dlab, float* __restrict__ o_displ) {
    int p    = blockIdx.x * 8 + (threadIdx.x >> 5);
    int lane = threadIdx.x & 31;
    int a    = g_assign[p];

    const float2* lr = (const float2*)(labels + (size_t)p * LL);
    const float2* rr = (const float2*)(rl     + (size_t)a * LL);
    float nn = 0.f, dd = 0.f, n1 = 0.f;
    for (int i = lane; i < LL / 2; i += 32) {
        float2 lv = lr[i];
        float2 rv = rr[i];
        nn = fmaf(lv.x, lv.x, nn); nn = fmaf(lv.y, lv.y, nn);
        dd = fmaf(lv.x, rv.x, dd); dd = fmaf(lv.y, rv.y, dd);
        n1 = fmaf(rv.x, rv.x, n1); n1 = fmaf(rv.y, rv.y, n1);
    }
    #pragma unroll
    for (int o = 16; o; o >>= 1) {
        nn += __shfl_xor_sync(0xffffffffu, nn, o);
        dd += __shfl_xor_sync(0xffffffffu, dd, o);
        n1 += __shfl_xor_sync(0xffffffffu, n1, o);
    }
    float dl = 1.f - dd / (sqrtf(nn) * sqrtf(n1) + 1e-8f);

    if (!lane) {
        o_dlab[p] = dl;
        atomicAdd(&o_displ[a], dl);
        int pos = atomicAdd(&g_cursor[a], 1);
        g_order[pos] = p;
    }
}

// ============================================================
// K5: per-cluster atomic-free segment sums (new_sum, new_labels)
// ============================================================
__global__ void __launch_bounds__(256)
cluster_kernel(const float* __restrict__ pts, const float* __restrict__ labels,
               float* __restrict__ o_nsum, float* __restrict__ o_nlab) {
    int k    = blockIdx.x;
    int t    = threadIdx.x;
    int cnt  = g_count[k];
    int base = g_offset[k];

    float sd = 0.f, l0 = 0.f, l1 = 0.f, l2 = 0.f;
    int p = (cnt > 0) ? g_order[base] : 0;
    for (int m = 0; m < cnt; ++m) {
        int pn = (m + 1 < cnt) ? g_order[base + m + 1] : 0;
        const float* prow = pts    + (size_t)p * DD;
        const float* lrow = labels + (size_t)p * LL;
        sd += prow[t];
        l0 += lrow[t];
        l1 += lrow[t + 256];
        if (t < LL - 512) l2 += lrow[t + 512];
        p = pn;
    }
    o_nsum[(size_t)k * DD + t] = sd;
    o_nlab[(size_t)k * LL + t]       = l0;
    o_nlab[(size_t)k * LL + t + 256] = l1;
    if (t < LL - 512) o_nlab[(size_t)k * LL + t + 512] = l2;
}

// ============================================================
// launch
// ============================================================
extern "C" void kernel_launch(void* const* d_in, const int* in_sizes, int n_in,
                              void* d_out, int out_size) {
    const float* pts  = (const float*)d_in[0];
    const float* labs = (const float*)d_in[1];
    const float* cent = (const float*)d_in[2];
    const float* rl   = (const float*)d_in[3];
    float* out = (float*)d_out;

    // output layout (reference return order, flattened)
    float* o_assign = out;                                 // B
    float* o_dist   = o_assign + BB;                       // B
    float* o_disp   = o_dist   + BB;                       // K
    float* o_dlab   = o_disp   + KK;                       // B
    float* o_displ  = o_dlab   + BB;                       // K
    float* o_nsum   = o_displ  + KK;                       // K*D
    float* o_nn     = o_nsum   + (size_t)KK * DD;          // K
    float* o_nlab   = o_nn     + KK;                       // K*L

    void* p_count = nullptr;
    cudaGetSymbolAddress(&p_count, g_count);
    cudaMemsetAsync(p_count, 0, KK * sizeof(int));
    cudaMemsetAsync(o_disp,  0, KK * sizeof(float));
    cudaMemsetAsync(o_displ, 0, KK * sizeof(float));

    c2bf_kernel<<<KK / 8, 256>>>(cent);

    cudaFuncSetAttribute(assign_kernel,
                         cudaFuncAttributeMaxDynamicSharedMemorySize, SMEM_REQ);
    assign_kernel<<<BB / 128, 256, SMEM_REQ>>>(pts, o_assign, o_dist, o_disp);

    scan_kernel<<<1, KK>>>(o_nn);

    label_kernel<<<BB / 8, 256>>>(labs, rl, o_dlab, o_displ);

    cluster_kernel<<<KK, 256>>>(pts, labs, o_nsum, o_nlab);
}

// round 15
// speedup vs baseline: 1.0180x; 1.0180x over previous
#include <cuda_runtime.h>
#include <cuda_bf16.h>
#include <math.h>
#include <stdint.h>

// Problem dims (fixed by the bench)
#define BB 131072
#define DD 256
#define KK 1024
#define LL 526

// -------- device scratch (no allocations allowed) --------
__device__ int   g_assign[BB];
__device__ int   g_count[KK];
__device__ int   g_offset[KK];
__device__ int   g_cursor[KK];
__device__ int   g_order[BB];
__device__ float g_c2[KK];
__device__ __align__(16) __nv_bfloat16 g_cbf[KK * 512];   // [k][hi 256 | lo 256]

// ============================================================
// helpers
// ============================================================
__device__ __forceinline__ uint32_t smem_u32(const void* p) {
    uint32_t a;
    asm("{ .reg .u64 t; cvta.to.shared.u64 t, %1; cvt.u32.u64 %0, t; }" : "=r"(a) : "l"(p));
    return a;
}
__device__ __forceinline__ void ldsm4(uint32_t* r, uint32_t addr) {
    asm volatile("ldmatrix.sync.aligned.m8n8.x4.shared.b16 {%0,%1,%2,%3}, [%4];"
                 : "=r"(r[0]), "=r"(r[1]), "=r"(r[2]), "=r"(r[3]) : "r"(addr));
}
__device__ __forceinline__ void mma16816(float* c, const uint32_t* a, const uint32_t* b) {
    asm volatile("mma.sync.aligned.m16n8k16.row.col.f32.bf16.bf16.f32 "
                 "{%0,%1,%2,%3}, {%4,%5,%6,%7}, {%8,%9}, {%0,%1,%2,%3};"
                 : "+f"(c[0]), "+f"(c[1]), "+f"(c[2]), "+f"(c[3])
                 : "r"(a[0]), "r"(a[1]), "r"(a[2]), "r"(a[3]), "r"(b[0]), "r"(b[1]));
}
__device__ __forceinline__ void sts64(uint32_t addr, uint32_t a, uint32_t b) {
    asm volatile("st.shared.v2.b32 [%0], {%1,%2};" :: "r"(addr), "r"(a), "r"(b) : "memory");
}
__device__ __forceinline__ void sts128(uint32_t addr, uint4 v) {
    asm volatile("st.shared.v4.b32 [%0], {%1,%2,%3,%4};"
                 :: "r"(addr), "r"(v.x), "r"(v.y), "r"(v.z), "r"(v.w) : "memory");
}
__device__ __forceinline__ void sts32(uint32_t addr, uint32_t v) {
    asm volatile("st.shared.b32 [%0], %1;" :: "r"(addr), "r"(v) : "memory");
}
__device__ __forceinline__ float lds_f(uint32_t addr) {
    float v; asm volatile("ld.shared.f32 %0, [%1];" : "=f"(v) : "r"(addr)); return v;
}
__device__ __forceinline__ void lds64(uint32_t addr, uint32_t& a, uint32_t& b) {
    asm volatile("ld.shared.v2.b32 {%0,%1}, [%2];" : "=r"(a), "=r"(b) : "r"(addr));
}
__device__ __forceinline__ uint32_t pack_bf2(float a, float b) {
    __nv_bfloat162 h = __floats2bfloat162_rn(a, b);   // .x = a (low 16 bits)
    return *(uint32_t*)&h;
}

// ============================================================
// K1: centroid norms (fp32) + bf16 hi/lo split table
// ============================================================
__global__ void c2bf_kernel(const float* __restrict__ cent) {
    int k    = blockIdx.x * 8 + (threadIdx.x >> 5);
    int lane = threadIdx.x & 31;
    const float4* row = (const float4*)(cent + (size_t)k * DD);
    __nv_bfloat16* hi = g_cbf + (size_t)k * 512;
    __nv_bfloat16* lo = hi + 256;
    float s = 0.f;
    #pragma unroll
    for (int i = 0; i < 2; ++i) {
        int f4 = lane + 32 * i;
        float4 v = row[f4];
        s = fmaf(v.x, v.x, s); s = fmaf(v.y, v.y, s);
        s = fmaf(v.z, v.z, s); s = fmaf(v.w, v.w, s);
        int d = f4 * 4;
        __nv_bfloat16 h0 = __float2bfloat16(v.x), h1 = __float2bfloat16(v.y);
        __nv_bfloat16 h2 = __float2bfloat16(v.z), h3 = __float2bfloat16(v.w);
        hi[d] = h0; hi[d+1] = h1; hi[d+2] = h2; hi[d+3] = h3;
        lo[d]   = __float2bfloat16(v.x - __bfloat162float(h0));
        lo[d+1] = __float2bfloat16(v.y - __bfloat162float(h1));
        lo[d+2] = __float2bfloat16(v.z - __bfloat162float(h2));
        lo[d+3] = __float2bfloat16(v.w - __bfloat162float(h3));
    }
    #pragma unroll
    for (int o = 16; o; o >>= 1) s += __shfl_xor_sync(0xffffffffu, s, o);
    if (!lane) g_c2[k] = s;
}

// ============================================================
// K2: bf16 hi/lo mma.sync distance GEMM + argmin
//   CTA = 128 points. A[128][512] bf16 swizzled K-major rows (1024B stride).
//   16 N-tiles of 64 centroids. Warps: 4 (m) x 2 (n), warp tile m32 x n32.
//   Per k16-step: 8 ldmatrix.x4 + 24 mma (hi*hi, hi*lo, lo*hi).
// ============================================================
#define A_OFF   0
#define A_BYTES (128 * 1024)
#define B_OFF   A_BYTES
#define B_BYTES (64 * 1024)
#define SC2_OFF (B_OFF + B_BYTES)          // 64 floats
#define X2_OFF  (SC2_OFF + 256)            // 128 floats
#define RED_OFF (X2_OFF + 512)             // 128 rows x 2 slots x 8B
#define SMEM_REQ (RED_OFF + 2048)

__global__ void __launch_bounds__(256, 1)
assign_kernel(const float* __restrict__ pts,
              float* __restrict__ o_assign, float* __restrict__ o_dist,
              float* __restrict__ o_disp) {
    extern __shared__ char smraw[];
    const uint32_t smb = smem_u32(smraw);
    const uint32_t smA = smb + A_OFF;
    const uint32_t smB = smb + B_OFF;
    const uint32_t smC2 = smb + SC2_OFF;
    const uint32_t smX2 = smb + X2_OFF;
    const uint32_t smRD = smb + RED_OFF;

    const int t    = threadIdx.x;
    const int wid  = t >> 5;
    const int lane = t & 31;
    const int blk  = blockIdx.x;

    // ---- A fill: fp32 -> bf16 hi/lo, swizzled; also x2 per point ----
    {
        const float4* src = (const float4*)(pts + (size_t)blk * 128 * DD);
        #pragma unroll
        for (int it = 0; it < 16; ++it) {
            int r = it * 8 + wid;
            uint32_t rowb = smA + r * 1024;
            uint32_t x = (uint32_t)((r & 7) << 4);
            float x2 = 0.f;
            #pragma unroll
            for (int h = 0; h < 2; ++h) {
                int f4 = h * 32 + lane;
                float4 v = src[r * 64 + f4];
                x2 = fmaf(v.x, v.x, x2); x2 = fmaf(v.y, v.y, x2);
                x2 = fmaf(v.z, v.z, x2); x2 = fmaf(v.w, v.w, x2);
                __nv_bfloat16 h0 = __float2bfloat16(v.x), h1 = __float2bfloat16(v.y);
                __nv_bfloat16 h2 = __float2bfloat16(v.z), h3 = __float2bfloat16(v.w);
                uint32_t hiA, hiB;
                { __nv_bfloat162 p(h0, h1); hiA = *(uint32_t*)&p; }
                { __nv_bfloat162 p(h2, h3); hiB = *(uint32_t*)&p; }
                uint32_t loA = pack_bf2(v.x - __bfloat162float(h0),
                                        v.y - __bfloat162float(h1));
                uint32_t loB = pack_bf2(v.z - __bfloat162float(h2),
                                        v.w - __bfloat162float(h3));
                uint32_t kb = (uint32_t)(f4 * 8);            // hi byte offset
                sts64(rowb + (kb ^ x), hiA, hiB);
                sts64(rowb + ((512 + kb) ^ x), loA, loB);
            }
            #pragma unroll
            for (int o = 16; o; o >>= 1) x2 += __shfl_xor_sync(0xffffffffu, x2, o);
            if (!lane) sts32(smX2 + r * 4, __float_as_uint(x2));
        }
    }

    // warp tiling: 4 m-groups x 2 n-groups
    const int wm = wid & 3;            // m0 = wm*32
    const int wn = wid >> 2;           // n0 = wn*32
    const int m0 = wm * 32;
    const int n0 = wn * 32;

    // ldmatrix lane addressing (loop-invariant parts)
    const int ar  = m0 + (lane & 15);
    const uint32_t aAdr = smA + ar * 1024;
    const uint32_t ax   = (uint32_t)((ar & 7) << 4);
    const uint32_t acA  = (uint32_t)((lane >> 4) << 4);
    const int br  = n0 + ((lane & 7) + ((lane >> 4) << 3));
    const uint32_t bAdr = smB + br * 1024;
    const uint32_t bx   = (uint32_t)((br & 7) << 4);
    const uint32_t bcA  = (uint32_t)(((lane >> 3) & 1) << 4);

    float acc[2][4][4];
    #pragma unroll
    for (int i = 0; i < 2; ++i)
        #pragma unroll
        for (int j = 0; j < 4; ++j)
            #pragma unroll
            for (int e = 0; e < 4; ++e) acc[i][j][e] = 0.f;

    float minv[2][2];
    int   mini[2][2];
    #pragma unroll
    for (int i = 0; i < 2; ++i)
        #pragma unroll
        for (int j = 0; j < 2; ++j) { minv[i][j] = 3.4e38f; mini[i][j] = 0; }

    for (int tile = 0; tile < 16; ++tile) {
        __syncthreads();   // epilogue of prev tile done before overwriting B/sc2
        // ---- B fill: 64 centroids x 1024B from g_cbf (hi|lo contiguous) ----
        {
            const uint4* src = (const uint4*)g_cbf + (size_t)(tile * 64) * 64;
            #pragma unroll
            for (int i = 0; i < 16; ++i) {
                int idx = i * 256 + t;
                int n  = idx >> 6;
                int ch = idx & 63;
                uint4 v = src[idx];
                sts128(smB + n * 1024 + (((uint32_t)(ch * 16)) ^ ((n & 7) << 4)), v);
            }
            if (t < 64) sts32(smC2 + t * 4, __float_as_uint(g_c2[tile * 64 + t]));
        }
        __syncthreads();

        // ---- mainloop: 16 k-steps of 16 ----
        #pragma unroll 2
        for (int ks = 0; ks < 16; ++ks) {
            uint32_t khb = (uint32_t)(ks * 32);
            uint32_t ah[2][4], al[2][4], bh[2][4], bl[2][4];
            ldsm4(ah[0], aAdr +         ((khb + acA) ^ ax));
            ldsm4(ah[1], aAdr + 16384 + ((khb + acA) ^ ax));
            ldsm4(al[0], aAdr +         ((512 + khb + acA) ^ ax));
            ldsm4(al[1], aAdr + 16384 + ((512 + khb + acA) ^ ax));
            ldsm4(bh[0], bAdr +         ((khb + bcA) ^ bx));
            ldsm4(bh[1], bAdr + 16384 + ((khb + bcA) ^ bx));
            ldsm4(bl[0], bAdr +         ((512 + khb + bcA) ^ bx));
            ldsm4(bl[1], bAdr + 16384 + ((512 + khb + bcA) ^ bx));
            // hi*hi
            #pragma unroll
            for (int mf = 0; mf < 2; ++mf)
                #pragma unroll
                for (int nf = 0; nf < 4; ++nf)
                    mma16816(acc[mf][nf], ah[mf], &bh[nf >> 1][(nf & 1) * 2]);
            // hi_a * lo_b
            #pragma unroll
            for (int mf = 0; mf < 2; ++mf)
                #pragma unroll
                for (int nf = 0; nf < 4; ++nf)
                    mma16816(acc[mf][nf], ah[mf], &bl[nf >> 1][(nf & 1) * 2]);
            // lo_a * hi_b
            #pragma unroll
            for (int mf = 0; mf < 2; ++mf)
                #pragma unroll
                for (int nf = 0; nf < 4; ++nf)
                    mma16816(acc[mf][nf], al[mf], &bh[nf >> 1][(nf & 1) * 2]);
        }

        // ---- epilogue: scores = c2 - 2*dot, running argmin; reset acc ----
        #pragma unroll
        for (int mf = 0; mf < 2; ++mf)
            #pragma unroll
            for (int nf = 0; nf < 4; ++nf) {
                int colb = n0 + nf * 8 + (lane & 3) * 2;   // within tile (0..63)
                float c20 = lds_f(smC2 + colb * 4);
                float c21 = lds_f(smC2 + colb * 4 + 4);
                int g0 = tile * 64 + colb;
                float* c = acc[mf][nf];
                float v0 = c20 - 2.f * c[0];
                float v1 = c21 - 2.f * c[1];
                float v2 = c20 - 2.f * c[2];
                float v3 = c21 - 2.f * c[3];
                if (v0 < minv[mf][0] || (v0 == minv[mf][0] && g0     < mini[mf][0])) { minv[mf][0] = v0; mini[mf][0] = g0; }
                if (v1 < minv[mf][0] || (v1 == minv[mf][0] && g0 + 1 < mini[mf][0])) { minv[mf][0] = v1; mini[mf][0] = g0 + 1; }
                if (v2 < minv[mf][1] || (v2 == minv[mf][1] && g0     < mini[mf][1])) { minv[mf][1] = v2; mini[mf][1] = g0; }
                if (v3 < minv[mf][1] || (v3 == minv[mf][1] && g0 + 1 < mini[mf][1])) { minv[mf][1] = v3; mini[mf][1] = g0 + 1; }
                c[0] = 0.f; c[1] = 0.f; c[2] = 0.f; c[3] = 0.f;
            }
    }

    // ---- reduce argmin: intra-warp over lane&3, then cross n-warp via smem ----
    #pragma unroll
    for (int off = 1; off < 4; off <<= 1) {
        #pragma unroll
        for (int mf = 0; mf < 2; ++mf)
            #pragma unroll
            for (int rh = 0; rh < 2; ++rh) {
                float ov = __shfl_xor_sync(0xffffffffu, minv[mf][rh], off);
                int   oi = __shfl_xor_sync(0xffffffffu, mini[mf][rh], off);
                if (ov < minv[mf][rh] || (ov == minv[mf][rh] && oi < mini[mf][rh])) {
                    minv[mf][rh] = ov; mini[mf][rh] = oi;
                }
            }
    }
    if ((lane & 3) == 0) {
        #pragma unroll
        for (int mf = 0; mf < 2; ++mf)
            #pragma unroll
            for (int rh = 0; rh < 2; ++rh) {
                int row = m0 + mf * 16 + rh * 8 + (lane >> 2);
                sts64(smRD + (row * 2 + wn) * 8,
                      __float_as_uint(minv[mf][rh]), (uint32_t)mini[mf][rh]);
            }
    }
    __syncthreads();

    if (t < 128) {
        uint32_t v0u, i0u, v1u, i1u;
        lds64(smRD + (t * 2 + 0) * 8, v0u, i0u);
        lds64(smRD + (t * 2 + 1) * 8, v1u, i1u);
        float v0 = __uint_as_float(v0u), v1 = __uint_as_float(v1u);
        int   i0 = (int)i0u,             i1 = (int)i1u;
        float bv = v0; int bi = i0;
        if (v1 < bv || (v1 == bv && i1 < bi)) { bv = v1; bi = i1; }

        int p = blk * 128 + t;
        o_assign[p] = (float)bi;
        g_assign[p] = bi;
        float dist = bv + lds_f(smX2 + t * 4);
        o_dist[p] = dist;
        atomicAdd(&o_disp[bi], dist);
        atomicAdd(&g_count[bi], 1);
    }
}

// ============================================================
// K3: exclusive scan of cluster counts (single block) + new_n output
// ============================================================
__global__ void scan_kernel(float* __restrict__ o_nn) {
    __shared__ int sc[KK];
    int t = threadIdx.x;
    int v = g_count[t];
    o_nn[t] = (float)v;
    sc[t] = v;
    __syncthreads();
    for (int o = 1; o < KK; o <<= 1) {
        int add = (t >= o) ? sc[t - o] : 0;
        __syncthreads();
        sc[t] += add;
        __syncthreads();
    }
    int excl = sc[t] - v;
    g_offset[t] = excl;
    g_cursor[t] = excl;
}

// ============================================================
// K4: per-point labels cosine + dispersion_labels + bucket scatter
// ============================================================
__global__ void __launch_bounds__(256)
label_kernel(const float* __restrict__ labels, const float* __restrict__ rl,
             float* __restrict__ o_dlab, float* __restrict__ o_displ) {
    int p    = blockIdx.x * 8 + (threadIdx.x >> 5);
    int lane = threadIdx.x & 31;
    int a    = g_assign[p];

    const float2* lr = (const float2*)(labels + (size_t)p * LL);
    const float2* rr = (const float2*)(rl     + (size_t)a * LL);
    float nn = 0.f, dd = 0.f, n1 = 0.f;
    for (int i = lane; i < LL / 2; i += 32) {
        float2 lv = lr[i];
        float2 rv = rr[i];
        nn = fmaf(lv.x, lv.x, nn); nn = fmaf(lv.y, lv.y, nn);
        dd = fmaf(lv.x, rv.x, dd); dd = fmaf(lv.y, rv.y, dd);
        n1 = fmaf(rv.x, rv.x, n1); n1 = fmaf(rv.y, rv.y, n1);
    }
    #pragma unroll
    for (int o = 16; o; o >>= 1) {
        nn += __shfl_xor_sync(0xffffffffu, nn, o);
        dd += __shfl_xor_sync(0xffffffffu, dd, o);
        n1 += __shfl_xor_sync(0xffffffffu, n1, o);
    }
    float dl = 1.f - dd / (sqrtf(nn) * sqrtf(n1) + 1e-8f);

    if (!lane) {
        o_dlab[p] = dl;
        atomicAdd(&o_displ[a], dl);
        int pos = atomicAdd(&g_cursor[a], 1);
        g_order[pos] = p;
    }
}

// ============================================================
// K5: per-cluster atomic-free segment sums (new_sum, new_labels)
// ============================================================
__global__ void __launch_bounds__(256)
cluster_kernel(const float* __restrict__ pts, const float* __restrict__ labels,
               float* __restrict__ o_nsum, float* __restrict__ o_nlab) {
    int k    = blockIdx.x;
    int t    = threadIdx.x;
    int cnt  = g_count[k];
    int base = g_offset[k];

    float sd = 0.f, l0 = 0.f, l1 = 0.f, l2 = 0.f;
    int p = (cnt > 0) ? g_order[base] : 0;
    for (int m = 0; m < cnt; ++m) {
        int pn = (m + 1 < cnt) ? g_order[base + m + 1] : 0;
        const float* prow = pts    + (size_t)p * DD;
        const float* lrow = labels + (size_t)p * LL;
        sd += prow[t];
        l0 += lrow[t];
        l1 += lrow[t + 256];
        if (t < LL - 512) l2 += lrow[t + 512];
        p = pn;
    }
    o_nsum[(size_t)k * DD + t] = sd;
    o_nlab[(size_t)k * LL + t]       = l0;
    o_nlab[(size_t)k * LL + t + 256] = l1;
    if (t < LL - 512) o_nlab[(size_t)k * LL + t + 512] = l2;
}

// ============================================================
// launch
// ============================================================
extern "C" void kernel_launch(void* const* d_in, const int* in_sizes, int n_in,
                              void* d_out, int out_size) {
    const float* pts  = (const float*)d_in[0];
    const float* labs = (const float*)d_in[1];
    const float* cent = (const float*)d_in[2];
    const float* rl   = (const float*)d_in[3];
    float* out = (float*)d_out;

    // output layout (reference return order, flattened)
    float* o_assign = out;                                 // B
    float* o_dist   = o_assign + BB;                       // B
    float* o_disp   = o_dist   + BB;                       // K
    float* o_dlab   = o_disp   + KK;                       // B
    float* o_displ  = o_dlab   + BB;                       // K
    float* o_nsum   = o_displ  + KK;                       // K*D
    float* o_nn     = o_nsum   + (size_t)KK * DD;          // K
    float* o_nlab   = o_nn     + KK;                       // K*L

    void* p_count = nullptr;
    cudaGetSymbolAddress(&p_count, g_count);
    cudaMemsetAsync(p_count, 0, KK * sizeof(int));
    cudaMemsetAsync(o_disp,  0, KK * sizeof(float));
    cudaMemsetAsync(o_displ, 0, KK * sizeof(float));

    c2bf_kernel<<<KK / 8, 256>>>(cent);

    cudaFuncSetAttribute(assign_kernel,
                         cudaFuncAttributeMaxDynamicSharedMemorySize, SMEM_REQ);
    assign_kernel<<<BB / 128, 256, SMEM_REQ>>>(pts, o_assign, o_dist, o_disp);

    scan_kernel<<<1, KK>>>(o_nn);

    label_kernel<<<BB / 8, 256>>>(labs, rl, o_dlab, o_displ);

    cluster_kernel<<<KK, 256>>>(pts, labs, o_nsum, o_nlab);
}

// round 16
// speedup vs baseline: 1.0750x; 1.0560x over previous
#include <cuda_runtime.h>
#include <cuda_bf16.h>
#include <math.h>
#include <stdint.h>

// Problem dims (fixed by the bench)
#define BB 131072
#define DD 256
#define KK 1024
#define LL 526
#define CAND_CAP 24
#define SLACK 0.0625f

// -------- device scratch (no allocations allowed) --------
__device__ int   g_assign[BB];
__device__ int   g_count[KK];
__device__ int   g_offset[KK];
__device__ int   g_cursor[KK];
__device__ int   g_order[BB];
__device__ float g_c2[KK];
__device__ int   g_ccnt[BB];
__device__ unsigned short g_cand[BB * CAND_CAP];
__device__ __align__(16) float4 g_cmeta[KK];                 // {c2, nhi_b, nlo_b, 0}
__device__ __align__(16) __nv_bfloat16 g_cbf_hi[KK * 256];   // hi halves, k-contiguous

// ============================================================
// helpers
// ============================================================
__device__ __forceinline__ uint32_t smem_u32(const void* p) {
    uint32_t a;
    asm("{ .reg .u64 t; cvta.to.shared.u64 t, %1; cvt.u32.u64 %0, t; }" : "=r"(a) : "l"(p));
    return a;
}
__device__ __forceinline__ void ldsm4(uint32_t* r, uint32_t addr) {
    asm volatile("ldmatrix.sync.aligned.m8n8.x4.shared.b16 {%0,%1,%2,%3}, [%4];"
                 : "=r"(r[0]), "=r"(r[1]), "=r"(r[2]), "=r"(r[3]) : "r"(addr));
}
__device__ __forceinline__ void mma16816(float* c, const uint32_t* a, const uint32_t* b) {
    asm volatile("mma.sync.aligned.m16n8k16.row.col.f32.bf16.bf16.f32 "
                 "{%0,%1,%2,%3}, {%4,%5,%6,%7}, {%8,%9}, {%0,%1,%2,%3};"
                 : "+f"(c[0]), "+f"(c[1]), "+f"(c[2]), "+f"(c[3])
                 : "r"(a[0]), "r"(a[1]), "r"(a[2]), "r"(a[3]), "r"(b[0]), "r"(b[1]));
}
__device__ __forceinline__ void sts64(uint32_t addr, uint32_t a, uint32_t b) {
    asm volatile("st.shared.v2.b32 [%0], {%1,%2};" :: "r"(addr), "r"(a), "r"(b) : "memory");
}
__device__ __forceinline__ void cpasync16(uint32_t dst, const void* src) {
    asm volatile("cp.async.cg.shared.global [%0], [%1], 16;" :: "r"(dst), "l"(src) : "memory");
}
#define CP_COMMIT() asm volatile("cp.async.commit_group;" ::: "memory")
#define CP_WAIT1()  asm volatile("cp.async.wait_group 1;" ::: "memory")
#define CP_WAIT0()  asm volatile("cp.async.wait_group 0;" ::: "memory")

// ============================================================
// K1: centroid bf16 hi table + norms (c2, ||hi_b||, ||lo_b||)
// ============================================================
__global__ void c2bf_kernel(const float* __restrict__ cent) {
    int k    = blockIdx.x * 8 + (threadIdx.x >> 5);
    int lane = threadIdx.x & 31;
    const float4* row = (const float4*)(cent + (size_t)k * DD);
    uint32_t* hi = (uint32_t*)(g_cbf_hi + (size_t)k * 256);
    float s = 0.f, h2 = 0.f, r2 = 0.f;
    #pragma unroll
    for (int i = 0; i < 2; ++i) {
        int f4 = lane + 32 * i;
        float4 v = row[f4];
        __nv_bfloat16 b0 = __float2bfloat16(v.x), b1 = __float2bfloat16(v.y);
        __nv_bfloat16 b2 = __float2bfloat16(v.z), b3 = __float2bfloat16(v.w);
        float h0 = __bfloat162float(b0), h1 = __bfloat162float(b1);
        float h2f = __bfloat162float(b2), h3 = __bfloat162float(b3);
        s = fmaf(v.x, v.x, s); s = fmaf(v.y, v.y, s);
        s = fmaf(v.z, v.z, s); s = fmaf(v.w, v.w, s);
        h2 = fmaf(h0, h0, h2); h2 = fmaf(h1, h1, h2);
        h2 = fmaf(h2f, h2f, h2); h2 = fmaf(h3, h3, h2);
        float e0 = v.x - h0, e1 = v.y - h1, e2 = v.z - h2f, e3 = v.w - h3;
        r2 = fmaf(e0, e0, r2); r2 = fmaf(e1, e1, r2);
        r2 = fmaf(e2, e2, r2); r2 = fmaf(e3, e3, r2);
        __nv_bfloat162 pA(b0, b1), pB(b2, b3);
        hi[f4 * 2]     = *(uint32_t*)&pA;
        hi[f4 * 2 + 1] = *(uint32_t*)&pB;
    }
    #pragma unroll
    for (int o = 16; o; o >>= 1) {
        s  += __shfl_xor_sync(0xffffffffu, s,  o);
        h2 += __shfl_xor_sync(0xffffffffu, h2, o);
        r2 += __shfl_xor_sync(0xffffffffu, r2, o);
    }
    if (!lane) {
        g_c2[k] = s;
        g_cmeta[k] = make_float4(s, sqrtf(h2) * 1.0002f, sqrtf(r2) * 1.0002f + 1e-7f, 0.f);
    }
}

// ============================================================
// K2 (phase 1): hi*hi mma.sync GEMM + margin-safe candidate pruning
//   CTA = 128 points. A[128][256] bf16 hi (512B rows, XOR swizzle).
//   16 N-tiles x 64 centroids; B double-buffered via cp.async.
//   Warps 4(m) x 2(n); per k-step: 4 ldmatrix.x4 + 8 mma.
// ============================================================
#define A_OFF   0
#define A_BYTES (128 * 512)
#define B_OFF   A_BYTES
#define B_HALF  (64 * 512)
#define PP_OFF  (B_OFF + 2 * B_HALF)     // 128 x float2
#define UB_OFF  (PP_OFF + 1024)          // 128 x float
#define VM_OFF  (UB_OFF + 512)           // 128 x 2 x float
#define CC_OFF  (VM_OFF + 1024)          // 128 x int
#define CD_OFF  (CC_OFF + 512)           // 128 x 24 x u16
#define SMEM_REQ (CD_OFF + 6144 + 256)

__global__ void __launch_bounds__(256, 1)
assign_kernel(const float* __restrict__ pts) {
    extern __shared__ char smraw[];
    const uint32_t smb = smem_u32(smraw);
    const uint32_t smA = smb + A_OFF;
    const uint32_t smB = smb + B_OFF;
    float2* pp  = (float2*)(smraw + PP_OFF);
    float*  ubp = (float*)(smraw + UB_OFF);
    float*  vmp = (float*)(smraw + VM_OFF);
    int*    ccp = (int*)(smraw + CC_OFF);
    unsigned short* cdp = (unsigned short*)(smraw + CD_OFF);

    const int t    = threadIdx.x;
    const int wid  = t >> 5;
    const int lane = t & 31;
    const int blk  = blockIdx.x;

    // ---- A fill: fp32 -> bf16 hi (swizzled); exact ||hi_a||, ||a-hi_a|| ----
    {
        const float4* src = (const float4*)(pts + (size_t)blk * 128 * DD);
        #pragma unroll
        for (int it = 0; it < 16; ++it) {
            int r = it * 8 + wid;
            uint32_t rowb = smA + r * 512;
            uint32_t x = (uint32_t)((r & 7) << 4);
            float h2 = 0.f, r2 = 0.f;
            #pragma unroll
            for (int h = 0; h < 2; ++h) {
                int f4 = h * 32 + lane;
                float4 v = src[r * 64 + f4];
                __nv_bfloat16 b0 = __float2bfloat16(v.x), b1 = __float2bfloat16(v.y);
                __nv_bfloat16 b2 = __float2bfloat16(v.z), b3 = __float2bfloat16(v.w);
                float h0 = __bfloat162float(b0), h1 = __bfloat162float(b1);
                float hf2 = __bfloat162float(b2), h3 = __bfloat162float(b3);
                h2 = fmaf(h0, h0, h2); h2 = fmaf(h1, h1, h2);
                h2 = fmaf(hf2, hf2, h2); h2 = fmaf(h3, h3, h2);
                float e0 = v.x - h0, e1 = v.y - h1, e2 = v.z - hf2, e3 = v.w - h3;
                r2 = fmaf(e0, e0, r2); r2 = fmaf(e1, e1, r2);
                r2 = fmaf(e2, e2, r2); r2 = fmaf(e3, e3, r2);
                uint32_t hiA, hiB;
                { __nv_bfloat162 p(b0, b1); hiA = *(uint32_t*)&p; }
                { __nv_bfloat162 p(b2, b3); hiB = *(uint32_t*)&p; }
                sts64(rowb + (((uint32_t)(f4 * 8)) ^ x), hiA, hiB);
            }
            #pragma unroll
            for (int o = 16; o; o >>= 1) {
                h2 += __shfl_xor_sync(0xffffffffu, h2, o);
                r2 += __shfl_xor_sync(0xffffffffu, r2, o);
            }
            if (!lane) {
                float nh = sqrtf(h2), nl = sqrtf(r2);
                pp[r] = make_float2(2.0004f * (nh + nl), 2.0004f * nl + 1e-7f);
            }
        }
    }
    if (t < 128) { ubp[t] = 3.4e38f; ccp[t] = 0; }

    // warp tiling
    const int wm = wid & 3;
    const int wn = wid >> 2;
    const int m0 = wm * 32;
    const int n0 = wn * 32;

    const int ar  = m0 + (lane & 15);
    const uint32_t aAdr = smA + ar * 512;
    const uint32_t ax   = (uint32_t)((ar & 7) << 4);
    const uint32_t acA  = (uint32_t)((lane >> 4) << 4);
    const int br  = n0 + ((lane & 7) + ((lane >> 4) << 3));
    const uint32_t brOff = (uint32_t)(br * 512);
    const uint32_t bx   = (uint32_t)((br & 7) << 4);
    const uint32_t bcA  = (uint32_t)(((lane >> 3) & 1) << 4);

    // B prefetch (cp.async): 32KB per tile, 8 x 16B per thread
    auto bfill = [&](int tile, uint32_t dstbase) {
        const char* srcb = (const char*)g_cbf_hi + (size_t)tile * 64 * 512;
        #pragma unroll
        for (int i = 0; i < 8; ++i) {
            int idx = i * 256 + t;
            int n = idx >> 5, ch = idx & 31;
            cpasync16(dstbase + n * 512 + (((uint32_t)(ch * 16)) ^ ((n & 7) << 4)),
                      srcb + n * 512 + ch * 16);
        }
    };
    bfill(0, smB); CP_COMMIT();
    __syncthreads();

    // per-thread row margin scalars (4 rows: mf x rh)
    float prow1[2][2], prow2[2][2];
    #pragma unroll
    for (int mf = 0; mf < 2; ++mf)
        #pragma unroll
        for (int rh = 0; rh < 2; ++rh) {
            float2 v = pp[m0 + mf * 16 + rh * 8 + (lane >> 2)];
            prow1[mf][rh] = v.x; prow2[mf][rh] = v.y;
        }

    float acc[2][4][4];
    #pragma unroll
    for (int i = 0; i < 2; ++i)
        #pragma unroll
        for (int j = 0; j < 4; ++j)
            #pragma unroll
            for (int e = 0; e < 4; ++e) acc[i][j][e] = 0.f;

    int buf = 0;
    for (int tile = 0; tile < 16; ++tile) {
        if (tile < 15) { bfill(tile + 1, smB + (buf ^ 1) * B_HALF); CP_COMMIT(); CP_WAIT1(); }
        else CP_WAIT0();
        __syncthreads();
        const uint32_t bb = smB + buf * B_HALF + brOff;

        // ---- mainloop: 16 k-steps of 16 (hi*hi only) ----
        #pragma unroll 4
        for (int ks = 0; ks < 16; ++ks) {
            uint32_t khb = (uint32_t)(ks * 32);
            uint32_t ah[2][4], bh[2][4];
            ldsm4(ah[0], aAdr +        ((khb + acA) ^ ax));
            ldsm4(ah[1], aAdr + 8192 + ((khb + acA) ^ ax));
            ldsm4(bh[0], bb +          ((khb + bcA) ^ bx));
            ldsm4(bh[1], bb + 8192 +   ((khb + bcA) ^ bx));
            #pragma unroll
            for (int mf = 0; mf < 2; ++mf)
                #pragma unroll
                for (int nf = 0; nf < 4; ++nf)
                    mma16816(acc[mf][nf], ah[mf], &bh[nf >> 1][(nf & 1) * 2]);
        }

        // ---- epilogue pass 1: scores + per-row min(v+m) ----
        float4 meta[8];
        #pragma unroll
        for (int nf = 0; nf < 4; ++nf)
            #pragma unroll
            for (int h = 0; h < 2; ++h)
                meta[nf * 2 + h] = g_cmeta[tile * 64 + n0 + nf * 8 + (lane & 3) * 2 + h];

        #pragma unroll
        for (int mf = 0; mf < 2; ++mf)
            #pragma unroll
            for (int rh = 0; rh < 2; ++rh) {
                float vmmin = 3.4e38f;
                #pragma unroll
                for (int nf = 0; nf < 4; ++nf)
                    #pragma unroll
                    for (int h = 0; h < 2; ++h) {
                        float4 mt = meta[nf * 2 + h];
                        float v = mt.x - 2.f * acc[mf][nf][rh * 2 + h];
                        float m = fmaf(prow1[mf][rh], mt.z,
                                       fmaf(prow2[mf][rh], mt.y, SLACK));
                        acc[mf][nf][rh * 2 + h] = v;
                        vmmin = fminf(vmmin, v + m);
                    }
                vmmin = fminf(vmmin, __shfl_xor_sync(0xffffffffu, vmmin, 1));
                vmmin = fminf(vmmin, __shfl_xor_sync(0xffffffffu, vmmin, 2));
                if ((lane & 3) == 0)
                    vmp[(m0 + mf * 16 + rh * 8 + (lane >> 2)) * 2 + wn] = vmmin;
            }
        __syncthreads();
        if (t < 128)
            ubp[t] = fminf(ubp[t], fminf(vmp[t * 2], vmp[t * 2 + 1]));
        __syncthreads();

        // ---- filter: keep cols with v - m <= ub (guaranteed superset) ----
        #pragma unroll
        for (int mf = 0; mf < 2; ++mf)
            #pragma unroll
            for (int rh = 0; rh < 2; ++rh) {
                int row = m0 + mf * 16 + rh * 8 + (lane >> 2);
                float u = ubp[row];
                #pragma unroll
                for (int nf = 0; nf < 4; ++nf)
                    #pragma unroll
                    for (int h = 0; h < 2; ++h) {
                        float4 mt = meta[nf * 2 + h];
                        float v = acc[mf][nf][rh * 2 + h];
                        float m = fmaf(prow1[mf][rh], mt.z,
                                       fmaf(prow2[mf][rh], mt.y, SLACK));
                        if (v - m <= u) {
                            int col = tile * 64 + n0 + nf * 8 + (lane & 3) * 2 + h;
                            int pos = atomicAdd(&ccp[row], 1);
                            if (pos < CAND_CAP) cdp[row * CAND_CAP + pos] = (unsigned short)col;
                        }
                        acc[mf][nf][rh * 2 + h] = 0.f;
                    }
            }
        buf ^= 1;
    }
    __syncthreads();

    if (t < 128) {
        int p = blk * 128 + t;
        int cnt = ccp[t];
        g_ccnt[p] = cnt;
        int n = cnt < CAND_CAP ? cnt : CAND_CAP;
        for (int j = 0; j < n; ++j) g_cand[(size_t)p * CAND_CAP + j] = cdp[t * CAND_CAP + j];
    }
}

// ============================================================
// K2b (phase 2): exact fp32 refine over candidates (warp per point)
// ============================================================
__global__ void __launch_bounds__(128)
refine_kernel(const float* __restrict__ pts, const float* __restrict__ cent,
              float* __restrict__ o_assign, float* __restrict__ o_dist,
              float* __restrict__ o_disp) {
    int p    = blockIdx.x * 4 + (threadIdx.x >> 5);
    int lane = threadIdx.x & 31;
    const float4* pa = (const float4*)(pts + (size_t)p * DD);
    float4 a0 = pa[lane], a1 = pa[lane + 32];

    float best = 3.4e38f; int bi = KK;
    int cnt = g_ccnt[p];

    auto eval = [&](int c) {
        const float4* cb = (const float4*)(cent + (size_t)c * DD);
        float4 b0 = cb[lane], b1 = cb[lane + 32];
        float d = a0.x * b0.x;
        d = fmaf(a0.y, b0.y, d); d = fmaf(a0.z, b0.z, d); d = fmaf(a0.w, b0.w, d);
        d = fmaf(a1.x, b1.x, d); d = fmaf(a1.y, b1.y, d);
        d = fmaf(a1.z, b1.z, d); d = fmaf(a1.w, b1.w, d);
        #pragma unroll
        for (int o = 16; o; o >>= 1) d += __shfl_xor_sync(0xffffffffu, d, o);
        float s = g_c2[c] - 2.f * d;
        if (s < best || (s == best && c < bi)) { best = s; bi = c; }
    };

    if (cnt <= CAND_CAP) {
        for (int j = 0; j < cnt; ++j) eval((int)g_cand[(size_t)p * CAND_CAP + j]);
    } else {
        for (int c = 0; c < KK; ++c) eval(c);   // overflow fallback (rare)
    }

    // direct-form dist to the winner (matches reference formula)
    {
        const float4* cb = (const float4*)(cent + (size_t)bi * DD);
        float4 b0 = cb[lane], b1 = cb[lane + 32];
        float dx, d2 = 0.f;
        dx = a0.x - b0.x; d2 = fmaf(dx, dx, d2);
        dx = a0.y - b0.y; d2 = fmaf(dx, dx, d2);
        dx = a0.z - b0.z; d2 = fmaf(dx, dx, d2);
        dx = a0.w - b0.w; d2 = fmaf(dx, dx, d2);
        dx = a1.x - b1.x; d2 = fmaf(dx, dx, d2);
        dx = a1.y - b1.y; d2 = fmaf(dx, dx, d2);
        dx = a1.z - b1.z; d2 = fmaf(dx, dx, d2);
        dx = a1.w - b1.w; d2 = fmaf(dx, dx, d2);
        #pragma unroll
        for (int o = 16; o; o >>= 1) d2 += __shfl_xor_sync(0xffffffffu, d2, o);
        if (!lane) {
            o_assign[p] = (float)bi;
            g_assign[p] = bi;
            o_dist[p]   = d2;
            atomicAdd(&o_disp[bi], d2);
            atomicAdd(&g_count[bi], 1);
        }
    }
}

// ============================================================
// K3: exclusive scan of cluster counts (single block) + new_n output
// ============================================================
__global__ void scan_kernel(float* __restrict__ o_nn) {
    __shared__ int sc[KK];
    int t = threadIdx.x;
    int v = g_count[t];
    o_nn[t] = (float)v;
    sc[t] = v;
    __syncthreads();
    for (int o = 1; o < KK; o <<= 1) {
        int add = (t >= o) ? sc[t - o] : 0;
        __syncthreads();
        sc[t] += add;
        __syncthreads();
    }
    int excl = sc[t] - v;
    g_offset[t] = excl;
    g_cursor[t] = excl;
}

// ============================================================
// K4: per-point labels cosine + dispersion_labels + bucket scatter
// ============================================================
__global__ void __launch_bounds__(256)
label_kernel(const float* __restrict__ labels, const float* __restrict__ rl,
             float* __restrict__ o_dlab, float* __restrict__ o_displ) {
    int p    = blockIdx.x * 8 + (threadIdx.x >> 5);
    int lane = threadIdx.x & 31;
    int a    = g_assign[p];

    const float2* lr = (const float2*)(labels + (size_t)p * LL);
    const float2* rr = (const float2*)(rl     + (size_t)a * LL);
    float nn = 0.f, dd = 0.f, n1 = 0.f;
    for (int i = lane; i < LL / 2; i += 32) {
        float2 lv = lr[i];
        float2 rv = rr[i];
        nn = fmaf(lv.x, lv.x, nn); nn = fmaf(lv.y, lv.y, nn);
        dd = fmaf(lv.x, rv.x, dd); dd = fmaf(lv.y, rv.y, dd);
        n1 = fmaf(rv.x, rv.x, n1); n1 = fmaf(rv.y, rv.y, n1);
    }
    #pragma unroll
    for (int o = 16; o; o >>= 1) {
        nn += __shfl_xor_sync(0xffffffffu, nn, o);
        dd += __shfl_xor_sync(0xffffffffu, dd, o);
        n1 += __shfl_xor_sync(0xffffffffu, n1, o);
    }
    float dl = 1.f - dd / (sqrtf(nn) * sqrtf(n1) + 1e-8f);

    if (!lane) {
        o_dlab[p] = dl;
        atomicAdd(&o_displ[a], dl);
        int pos = atomicAdd(&g_cursor[a], 1);
        g_order[pos] = p;
    }
}

// ============================================================
// K5: per-cluster atomic-free segment sums (new_sum, new_labels)
// ============================================================
__global__ void __launch_bounds__(256)
cluster_kernel(const float* __restrict__ pts, const float* __restrict__ labels,
               float* __restrict__ o_nsum, float* __restrict__ o_nlab) {
    int k    = blockIdx.x;
    int t    = threadIdx.x;
    int cnt  = g_count[k];
    int base = g_offset[k];

    float sd = 0.f, l0 = 0.f, l1 = 0.f, l2 = 0.f;
    int p = (cnt > 0) ? g_order[base] : 0;
    for (int m = 0; m < cnt; ++m) {
        int pn = (m + 1 < cnt) ? g_order[base + m + 1] : 0;
        const float* prow = pts    + (size_t)p * DD;
        const float* lrow = labels + (size_t)p * LL;
        sd += prow[t];
        l0 += lrow[t];
        l1 += lrow[t + 256];
        if (t < LL - 512) l2 += lrow[t + 512];
        p = pn;
    }
    o_nsum[(size_t)k * DD + t] = sd;
    o_nlab[(size_t)k * LL + t]       = l0;
    o_nlab[(size_t)k * LL + t + 256] = l1;
    if (t < LL - 512) o_nlab[(size_t)k * LL + t + 512] = l2;
}

// ============================================================
// launch
// ============================================================
extern "C" void kernel_launch(void* const* d_in, const int* in_sizes, int n_in,
                              void* d_out, int out_size) {
    const float* pts  = (const float*)d_in[0];
    const float* labs = (const float*)d_in[1];
    const float* cent = (const float*)d_in[2];
    const float* rl   = (const float*)d_in[3];
    float* out = (float*)d_out;

    // output layout (reference return order, flattened)
    float* o_assign = out;                                 // B
    float* o_dist   = o_assign + BB;                       // B
    float* o_disp   = o_dist   + BB;                       // K
    float* o_dlab   = o_disp   + KK;                       // B
    float* o_displ  = o_dlab   + BB;                       // K
    float* o_nsum   = o_displ  + KK;                       // K*D
    float* o_nn     = o_nsum   + (size_t)KK * DD;          // K
    float* o_nlab   = o_nn     + KK;                       // K*L

    void* p_count = nullptr;
    cudaGetSymbolAddress(&p_count, g_count);
    cudaMemsetAsync(p_count, 0, KK * sizeof(int));
    cudaMemsetAsync(o_disp,  0, KK * sizeof(float));
    cudaMemsetAsync(o_displ, 0, KK * sizeof(float));

    c2bf_kernel<<<KK / 8, 256>>>(cent);

    cudaFuncSetAttribute(assign_kernel,
                         cudaFuncAttributeMaxDynamicSharedMemorySize, SMEM_REQ);
    assign_kernel<<<BB / 128, 256, SMEM_REQ>>>(pts);

    refine_kernel<<<BB / 4, 128>>>(pts, cent, o_assign, o_dist, o_disp);

    scan_kernel<<<1, KK>>>(o_nn);

    label_kernel<<<BB / 8, 256>>>(labs, rl, o_dlab, o_displ);

    cluster_kernel<<<KK, 256>>>(pts, labs, o_nsum, o_nlab);
}

// round 17
// speedup vs baseline: 1.1193x; 1.0412x over previous
#include <cuda_runtime.h>
#include <cuda_bf16.h>
#include <math.h>
#include <stdint.h>

// Problem dims (fixed by the bench)
#define BB 131072
#define DD 256
#define KK 1024
#define LL 526
#define CAND_CAP 24
#define SLACK 0.0625f

// -------- device scratch (no allocations allowed) --------
__device__ int   g_assign[BB];
__device__ int   g_count[KK];
__device__ int   g_offset[KK];
__device__ int   g_cursor[KK];
__device__ int   g_order[BB];
__device__ float g_c2[KK];
__device__ int   g_ccnt[BB];
__device__ unsigned short g_cand[BB * CAND_CAP];
__device__ __align__(16) float4 g_cmeta[KK];                 // {c2, nhi_b, nlo_b, 0}
__device__ __align__(16) __nv_bfloat16 g_cbf_hi[KK * 256];   // hi halves, k-contiguous

// ============================================================
// helpers
// ============================================================
__device__ __forceinline__ uint32_t smem_u32(const void* p) {
    uint32_t a;
    asm("{ .reg .u64 t; cvta.to.shared.u64 t, %1; cvt.u32.u64 %0, t; }" : "=r"(a) : "l"(p));
    return a;
}
__device__ __forceinline__ void ldsm4(uint32_t* r, uint32_t addr) {
    asm volatile("ldmatrix.sync.aligned.m8n8.x4.shared.b16 {%0,%1,%2,%3}, [%4];"
                 : "=r"(r[0]), "=r"(r[1]), "=r"(r[2]), "=r"(r[3]) : "r"(addr));
}
__device__ __forceinline__ void mma16816(float* c, const uint32_t* a, const uint32_t* b) {
    asm volatile("mma.sync.aligned.m16n8k16.row.col.f32.bf16.bf16.f32 "
                 "{%0,%1,%2,%3}, {%4,%5,%6,%7}, {%8,%9}, {%0,%1,%2,%3};"
                 : "+f"(c[0]), "+f"(c[1]), "+f"(c[2]), "+f"(c[3])
                 : "r"(a[0]), "r"(a[1]), "r"(a[2]), "r"(a[3]), "r"(b[0]), "r"(b[1]));
}
__device__ __forceinline__ void sts64(uint32_t addr, uint32_t a, uint32_t b) {
    asm volatile("st.shared.v2.b32 [%0], {%1,%2};" :: "r"(addr), "r"(a), "r"(b) : "memory");
}
__device__ __forceinline__ float4 lds128f(uint32_t addr) {
    float4 v;
    asm volatile("ld.shared.v4.f32 {%0,%1,%2,%3}, [%4];"
                 : "=f"(v.x), "=f"(v.y), "=f"(v.z), "=f"(v.w) : "r"(addr));
    return v;
}
__device__ __forceinline__ void cpasync16(uint32_t dst, const void* src) {
    asm volatile("cp.async.cg.shared.global [%0], [%1], 16;" :: "r"(dst), "l"(src) : "memory");
}
#define CP_COMMIT() asm volatile("cp.async.commit_group;" ::: "memory")
#define CP_WAIT1()  asm volatile("cp.async.wait_group 1;" ::: "memory")
#define CP_WAIT0()  asm volatile("cp.async.wait_group 0;" ::: "memory")

// ============================================================
// K1: centroid bf16 hi table + norms (c2, ||hi_b||, ||lo_b||)
// ============================================================
__global__ void c2bf_kernel(const float* __restrict__ cent) {
    int k    = blockIdx.x * 8 + (threadIdx.x >> 5);
    int lane = threadIdx.x & 31;
    const float4* row = (const float4*)(cent + (size_t)k * DD);
    uint32_t* hi = (uint32_t*)(g_cbf_hi + (size_t)k * 256);
    float s = 0.f, h2 = 0.f, r2 = 0.f;
    #pragma unroll
    for (int i = 0; i < 2; ++i) {
        int f4 = lane + 32 * i;
        float4 v = row[f4];
        __nv_bfloat16 b0 = __float2bfloat16(v.x), b1 = __float2bfloat16(v.y);
        __nv_bfloat16 b2 = __float2bfloat16(v.z), b3 = __float2bfloat16(v.w);
        float h0 = __bfloat162float(b0), h1 = __bfloat162float(b1);
        float h2f = __bfloat162float(b2), h3 = __bfloat162float(b3);
        s = fmaf(v.x, v.x, s); s = fmaf(v.y, v.y, s);
        s = fmaf(v.z, v.z, s); s = fmaf(v.w, v.w, s);
        h2 = fmaf(h0, h0, h2); h2 = fmaf(h1, h1, h2);
        h2 = fmaf(h2f, h2f, h2); h2 = fmaf(h3, h3, h2);
        float e0 = v.x - h0, e1 = v.y - h1, e2 = v.z - h2f, e3 = v.w - h3;
        r2 = fmaf(e0, e0, r2); r2 = fmaf(e1, e1, r2);
        r2 = fmaf(e2, e2, r2); r2 = fmaf(e3, e3, r2);
        __nv_bfloat162 pA(b0, b1), pB(b2, b3);
        hi[f4 * 2]     = *(uint32_t*)&pA;
        hi[f4 * 2 + 1] = *(uint32_t*)&pB;
    }
    #pragma unroll
    for (int o = 16; o; o >>= 1) {
        s  += __shfl_xor_sync(0xffffffffu, s,  o);
        h2 += __shfl_xor_sync(0xffffffffu, h2, o);
        r2 += __shfl_xor_sync(0xffffffffu, r2, o);
    }
    if (!lane) {
        g_c2[k] = s;
        g_cmeta[k] = make_float4(s, sqrtf(h2) * 1.0002f, sqrtf(r2) * 1.0002f + 1e-7f, 0.f);
    }
}

// ============================================================
// K2 (phase 1): hi*hi mma.sync GEMM + margin-safe candidate pruning
//   CTA = 128 points x 512 threads. A[128][256] bf16 hi (512B rows, swizzled).
//   8 N-tiles x 128 centroids; B double-buffered via cp.async.
//   Warps 4(m) x 4(n), warp tile 32x32. cmeta cached in smem.
// ============================================================
#define A_OFF    0
#define A_BYTES  (128 * 512)
#define B_OFF    A_BYTES
#define B_HALF   (128 * 512)
#define META_OFF (B_OFF + 2 * B_HALF)       // 1024 x float4 = 16KB
#define PP_OFF   (META_OFF + 16384)         // 128 x float2
#define VM_OFF   (PP_OFF + 1024)            // 128 x 4 x float
#define UB_OFF   (VM_OFF + 2048)            // 128 x float
#define CC_OFF   (UB_OFF + 512)             // 128 x int
#define CD_OFF   (CC_OFF + 512)             // 128 x 24 x u16
#define SMEM_REQ (CD_OFF + 6144 + 256)

__global__ void __launch_bounds__(512, 1)
assign_kernel(const float* __restrict__ pts) {
    extern __shared__ char smraw[];
    const uint32_t smb   = smem_u32(smraw);
    const uint32_t smA   = smb + A_OFF;
    const uint32_t smB   = smb + B_OFF;
    const uint32_t smMT  = smb + META_OFF;
    float2* pp  = (float2*)(smraw + PP_OFF);
    float*  vmp = (float*)(smraw + VM_OFF);
    float*  ubp = (float*)(smraw + UB_OFF);
    int*    ccp = (int*)(smraw + CC_OFF);
    unsigned short* cdp = (unsigned short*)(smraw + CD_OFF);

    const int t    = threadIdx.x;
    const int wid  = t >> 5;
    const int lane = t & 31;
    const int blk  = blockIdx.x;

    // ---- cmeta -> smem (16KB) ----
    {
        const float4* src = g_cmeta;
        float4 v0 = src[t * 2], v1 = src[t * 2 + 1];
        *(float4*)(smraw + META_OFF + t * 32)      = v0;
        *(float4*)(smraw + META_OFF + t * 32 + 16) = v1;
    }

    // ---- A fill: fp32 -> bf16 hi (swizzled); exact margin norms ----
    {
        const float4* src = (const float4*)(pts + (size_t)blk * 128 * DD);
        #pragma unroll
        for (int it = 0; it < 8; ++it) {
            int r = it * 16 + wid;
            uint32_t rowb = smA + r * 512;
            uint32_t x = (uint32_t)((r & 7) << 4);
            float h2 = 0.f, r2 = 0.f;
            #pragma unroll
            for (int h = 0; h < 2; ++h) {
                int f4 = h * 32 + lane;
                float4 v = src[r * 64 + f4];
                __nv_bfloat16 b0 = __float2bfloat16(v.x), b1 = __float2bfloat16(v.y);
                __nv_bfloat16 b2 = __float2bfloat16(v.z), b3 = __float2bfloat16(v.w);
                float h0 = __bfloat162float(b0), h1 = __bfloat162float(b1);
                float hf2 = __bfloat162float(b2), h3 = __bfloat162float(b3);
                h2 = fmaf(h0, h0, h2); h2 = fmaf(h1, h1, h2);
                h2 = fmaf(hf2, hf2, h2); h2 = fmaf(h3, h3, h2);
                float e0 = v.x - h0, e1 = v.y - h1, e2 = v.z - hf2, e3 = v.w - h3;
                r2 = fmaf(e0, e0, r2); r2 = fmaf(e1, e1, r2);
                r2 = fmaf(e2, e2, r2); r2 = fmaf(e3, e3, r2);
                uint32_t hiA, hiB;
                { __nv_bfloat162 p(b0, b1); hiA = *(uint32_t*)&p; }
                { __nv_bfloat162 p(b2, b3); hiB = *(uint32_t*)&p; }
                sts64(rowb + (((uint32_t)(f4 * 8)) ^ x), hiA, hiB);
            }
            #pragma unroll
            for (int o = 16; o; o >>= 1) {
                h2 += __shfl_xor_sync(0xffffffffu, h2, o);
                r2 += __shfl_xor_sync(0xffffffffu, r2, o);
            }
            if (!lane) {
                float nh = sqrtf(h2), nl = sqrtf(r2);
                pp[r] = make_float2(2.0004f * (nh + nl), 2.0004f * nl + 1e-7f);
            }
        }
    }
    if (t < 128) { ubp[t] = 3.4e38f; ccp[t] = 0; }

    // warp tiling: 4(m) x 4(n)
    const int wm = wid & 3;
    const int wn = wid >> 2;
    const int m0 = wm * 32;
    const int n0 = wn * 32;

    const int ar  = m0 + (lane & 15);
    const uint32_t aAdr = smA + ar * 512;
    const uint32_t ax   = (uint32_t)((ar & 7) << 4);
    const uint32_t acA  = (uint32_t)((lane >> 4) << 4);
    const int br  = n0 + ((lane & 7) + ((lane >> 4) << 3));
    const uint32_t brOff = (uint32_t)(br * 512);
    const uint32_t bx   = (uint32_t)((br & 7) << 4);
    const uint32_t bcA  = (uint32_t)(((lane >> 3) & 1) << 4);

    // B prefetch: 64KB per tile of 128 centroids, 8 x 16B per thread
    auto bfill = [&](int tile, uint32_t dstbase) {
        const char* srcb = (const char*)g_cbf_hi + (size_t)tile * 128 * 512;
        #pragma unroll
        for (int i = 0; i < 8; ++i) {
            int idx = i * 512 + t;
            int n = idx >> 5, ch = idx & 31;
            cpasync16(dstbase + n * 512 + (((uint32_t)(ch * 16)) ^ ((n & 7) << 4)),
                      srcb + n * 512 + ch * 16);
        }
    };
    bfill(0, smB); CP_COMMIT();
    __syncthreads();

    // per-thread row margin scalars
    float prow1[2][2], prow2[2][2];
    #pragma unroll
    for (int mf = 0; mf < 2; ++mf)
        #pragma unroll
        for (int rh = 0; rh < 2; ++rh) {
            float2 v = pp[m0 + mf * 16 + rh * 8 + (lane >> 2)];
            prow1[mf][rh] = v.x; prow2[mf][rh] = v.y;
        }

    float acc[2][4][4];
    #pragma unroll
    for (int i = 0; i < 2; ++i)
        #pragma unroll
        for (int j = 0; j < 4; ++j)
            #pragma unroll
            for (int e = 0; e < 4; ++e) acc[i][j][e] = 0.f;

    int buf = 0;
    for (int tile = 0; tile < 8; ++tile) {
        if (tile < 7) { bfill(tile + 1, smB + (buf ^ 1) * B_HALF); CP_COMMIT(); CP_WAIT1(); }
        else CP_WAIT0();
        __syncthreads();
        const uint32_t bb = smB + buf * B_HALF + brOff;

        // ---- mainloop: 16 k-steps of 16 (hi*hi only) ----
        #pragma unroll 4
        for (int ks = 0; ks < 16; ++ks) {
            uint32_t khb = (uint32_t)(ks * 32);
            uint32_t ah[2][4], bh[2][4];
            ldsm4(ah[0], aAdr +        ((khb + acA) ^ ax));
            ldsm4(ah[1], aAdr + 8192 + ((khb + acA) ^ ax));
            ldsm4(bh[0], bb +          ((khb + bcA) ^ bx));
            ldsm4(bh[1], bb + 8192 +   ((khb + bcA) ^ bx));
            #pragma unroll
            for (int mf = 0; mf < 2; ++mf)
                #pragma unroll
                for (int nf = 0; nf < 4; ++nf)
                    mma16816(acc[mf][nf], ah[mf], &bh[nf >> 1][(nf & 1) * 2]);
        }

        // ---- epilogue pass 1: scores + per-warp per-row min(v+m) ----
        float4 mt[8];
        #pragma unroll
        for (int nf = 0; nf < 4; ++nf)
            #pragma unroll
            for (int h = 0; h < 2; ++h)
                mt[nf * 2 + h] = lds128f(smMT +
                    (uint32_t)((tile * 128 + n0 + nf * 8 + (lane & 3) * 2 + h) * 16));

        #pragma unroll
        for (int mf = 0; mf < 2; ++mf)
            #pragma unroll
            for (int rh = 0; rh < 2; ++rh) {
                float vmmin = 3.4e38f;
                #pragma unroll
                for (int nf = 0; nf < 4; ++nf)
                    #pragma unroll
                    for (int h = 0; h < 2; ++h) {
                        float4 m4 = mt[nf * 2 + h];
                        float v = m4.x - 2.f * acc[mf][nf][rh * 2 + h];
                        float m = fmaf(prow1[mf][rh], m4.z,
                                       fmaf(prow2[mf][rh], m4.y, SLACK));
                        acc[mf][nf][rh * 2 + h] = v;
                        vmmin = fminf(vmmin, v + m);
                    }
                vmmin = fminf(vmmin, __shfl_xor_sync(0xffffffffu, vmmin, 1));
                vmmin = fminf(vmmin, __shfl_xor_sync(0xffffffffu, vmmin, 2));
                if ((lane & 3) == 0)
                    vmp[(m0 + mf * 16 + rh * 8 + (lane >> 2)) * 4 + wn] = vmmin;
            }
        __syncthreads();

        // ---- pass 2: combine ub, filter v - m <= ub (guaranteed superset) ----
        #pragma unroll
        for (int mf = 0; mf < 2; ++mf)
            #pragma unroll
            for (int rh = 0; rh < 2; ++rh) {
                int row = m0 + mf * 16 + rh * 8 + (lane >> 2);
                float4 vm4 = lds128f((uint32_t)(smb + VM_OFF + row * 16));
                float u = fminf(fminf(vm4.x, vm4.y), fminf(vm4.z, vm4.w));
                u = fminf(u, ubp[row]);
                #pragma unroll
                for (int nf = 0; nf < 4; ++nf)
                    #pragma unroll
                    for (int h = 0; h < 2; ++h) {
                        float4 m4 = mt[nf * 2 + h];
                        float v = acc[mf][nf][rh * 2 + h];
                        float m = fmaf(prow1[mf][rh], m4.z,
                                       fmaf(prow2[mf][rh], m4.y, SLACK));
                        if (v - m <= u) {
                            int col = tile * 128 + n0 + nf * 8 + (lane & 3) * 2 + h;
                            int pos = atomicAdd(&ccp[row], 1);
                            if (pos < CAND_CAP) cdp[row * CAND_CAP + pos] = (unsigned short)col;
                        }
                        acc[mf][nf][rh * 2 + h] = 0.f;
                    }
                if (wn == 0 && (lane & 3) == 0) ubp[row] = u;   // one writer; read next tile
            }
        buf ^= 1;
    }
    __syncthreads();

    if (t < 128) {
        int p = blk * 128 + t;
        int cnt = ccp[t];
        g_ccnt[p] = cnt;
        int n = cnt < CAND_CAP ? cnt : CAND_CAP;
        for (int j = 0; j < n; ++j) g_cand[(size_t)p * CAND_CAP + j] = cdp[t * CAND_CAP + j];
    }
}

// ============================================================
// K2b (phase 2): exact fp32 refine over candidates (warp per point)
// ============================================================
__global__ void __launch_bounds__(128)
refine_kernel(const float* __restrict__ pts, const float* __restrict__ cent,
              float* __restrict__ o_assign, float* __restrict__ o_dist,
              float* __restrict__ o_disp) {
    int p    = blockIdx.x * 4 + (threadIdx.x >> 5);
    int lane = threadIdx.x & 31;
    const float4* pa = (const float4*)(pts + (size_t)p * DD);
    float4 a0 = pa[lane], a1 = pa[lane + 32];

    float best = 3.4e38f; int bi = KK;
    int cnt = g_ccnt[p];

    auto eval = [&](int c) {
        const float4* cb = (const float4*)(cent + (size_t)c * DD);
        float4 b0 = cb[lane], b1 = cb[lane + 32];
        float d = a0.x * b0.x;
        d = fmaf(a0.y, b0.y, d); d = fmaf(a0.z, b0.z, d); d = fmaf(a0.w, b0.w, d);
        d = fmaf(a1.x, b1.x, d); d = fmaf(a1.y, b1.y, d);
        d = fmaf(a1.z, b1.z, d); d = fmaf(a1.w, b1.w, d);
        #pragma unroll
        for (int o = 16; o; o >>= 1) d += __shfl_xor_sync(0xffffffffu, d, o);
        float s = g_c2[c] - 2.f * d;
        if (s < best || (s == best && c < bi)) { best = s; bi = c; }
    };

    if (cnt <= CAND_CAP) {
        for (int j = 0; j < cnt; ++j) eval((int)g_cand[(size_t)p * CAND_CAP + j]);
    } else {
        for (int c = 0; c < KK; ++c) eval(c);   // overflow fallback (rare)
    }

    // direct-form dist to the winner (matches reference formula)
    {
        const float4* cb = (const float4*)(cent + (size_t)bi * DD);
        float4 b0 = cb[lane], b1 = cb[lane + 32];
        float dx, d2 = 0.f;
        dx = a0.x - b0.x; d2 = fmaf(dx, dx, d2);
        dx = a0.y - b0.y; d2 = fmaf(dx, dx, d2);
        dx = a0.z - b0.z; d2 = fmaf(dx, dx, d2);
        dx = a0.w - b0.w; d2 = fmaf(dx, dx, d2);
        dx = a1.x - b1.x; d2 = fmaf(dx, dx, d2);
        dx = a1.y - b1.y; d2 = fmaf(dx, dx, d2);
        dx = a1.z - b1.z; d2 = fmaf(dx, dx, d2);
        dx = a1.w - b1.w; d2 = fmaf(dx, dx, d2);
        #pragma unroll
        for (int o = 16; o; o >>= 1) d2 += __shfl_xor_sync(0xffffffffu, d2, o);
        if (!lane) {
            o_assign[p] = (float)bi;
            g_assign[p] = bi;
            o_dist[p]   = d2;
            atomicAdd(&o_disp[bi], d2);
            atomicAdd(&g_count[bi], 1);
        }
    }
}

// ============================================================
// K3: exclusive scan of cluster counts (single block) + new_n output
// ============================================================
__global__ void scan_kernel(float* __restrict__ o_nn) {
    __shared__ int sc[KK];
    int t = threadIdx.x;
    int v = g_count[t];
    o_nn[t] = (float)v;
    sc[t] = v;
    __syncthreads();
    for (int o = 1; o < KK; o <<= 1) {
        int add = (t >= o) ? sc[t - o] : 0;
        __syncthreads();
        sc[t] += add;
        __syncthreads();
    }
    int excl = sc[t] - v;
    g_offset[t] = excl;
    g_cursor[t] = excl;
}

// ============================================================
// K4: per-point labels cosine + dispersion_labels + bucket scatter
// ============================================================
__global__ void __launch_bounds__(256)
label_kernel(const float* __restrict__ labels, const float* __restrict__ rl,
             float* __restrict__ o_dlab, float* __restrict__ o_displ) {
    int p    = blockIdx.x * 8 + (threadIdx.x >> 5);
    int lane = threadIdx.x & 31;
    int a    = g_assign[p];

    const float2* lr = (const float2*)(labels + (size_t)p * LL);
    const float2* rr = (const float2*)(rl     + (size_t)a * LL);
    float nn = 0.f, dd = 0.f, n1 = 0.f;
    for (int i = lane; i < LL / 2; i += 32) {
        float2 lv = lr[i];
        float2 rv = rr[i];
        nn = fmaf(lv.x, lv.x, nn); nn = fmaf(lv.y, lv.y, nn);
        dd = fmaf(lv.x, rv.x, dd); dd = fmaf(lv.y, rv.y, dd);
        n1 = fmaf(rv.x, rv.x, n1); n1 = fmaf(rv.y, rv.y, n1);
    }
    #pragma unroll
    for (int o = 16; o; o >>= 1) {
        nn += __shfl_xor_sync(0xffffffffu, nn, o);
        dd += __shfl_xor_sync(0xffffffffu, dd, o);
        n1 += __shfl_xor_sync(0xffffffffu, n1, o);
    }
    float dl = 1.f - dd / (sqrtf(nn) * sqrtf(n1) + 1e-8f);

    if (!lane) {
        o_dlab[p] = dl;
        atomicAdd(&o_displ[a], dl);
        int pos = atomicAdd(&g_cursor[a], 1);
        g_order[pos] = p;
    }
}

// ============================================================
// K5: per-cluster atomic-free segment sums (new_sum, new_labels)
// ============================================================
__global__ void __launch_bounds__(256)
cluster_kernel(const float* __restrict__ pts, const float* __restrict__ labels,
               float* __restrict__ o_nsum, float* __restrict__ o_nlab) {
    int k    = blockIdx.x;
    int t    = threadIdx.x;
    int cnt  = g_count[k];
    int base = g_offset[k];

    float sd = 0.f, l0 = 0.f, l1 = 0.f, l2 = 0.f;
    int p = (cnt > 0) ? g_order[base] : 0;
    for (int m = 0; m < cnt; ++m) {
        int pn = (m + 1 < cnt) ? g_order[base + m + 1] : 0;
        const float* prow = pts    + (size_t)p * DD;
        const float* lrow = labels + (size_t)p * LL;
        sd += prow[t];
        l0 += lrow[t];
        l1 += lrow[t + 256];
        if (t < LL - 512) l2 += lrow[t + 512];
        p = pn;
    }
    o_nsum[(size_t)k * DD + t] = sd;
    o_nlab[(size_t)k * LL + t]       = l0;
    o_nlab[(size_t)k * LL + t + 256] = l1;
    if (t < LL - 512) o_nlab[(size_t)k * LL + t + 512] = l2;
}

// ============================================================
// launch
// ============================================================
extern "C" void kernel_launch(void* const* d_in, const int* in_sizes, int n_in,
                              void* d_out, int out_size) {
    const float* pts  = (const float*)d_in[0];
    const float* labs = (const float*)d_in[1];
    const float* cent = (const float*)d_in[2];
    const float* rl   = (const float*)d_in[3];
    float* out = (float*)d_out;

    // output layout (reference return order, flattened)
    float* o_assign = out;                                 // B
    float* o_dist   = o_assign + BB;                       // B
    float* o_disp   = o_dist   + BB;                       // K
    float* o_dlab   = o_disp   + KK;                       // B
    float* o_displ  = o_dlab   + BB;                       // K
    float* o_nsum   = o_displ  + KK;                       // K*D
    float* o_nn     = o_nsum   + (size_t)KK * DD;          // K
    float* o_nlab   = o_nn     + KK;                       // K*L

    void* p_count = nullptr;
    cudaGetSymbolAddress(&p_count, g_count);
    cudaMemsetAsync(p_count, 0, KK * sizeof(int));
    cudaMemsetAsync(o_disp,  0, KK * sizeof(float));
    cudaMemsetAsync(o_displ, 0, KK * sizeof(float));

    c2bf_kernel<<<KK / 8, 256>>>(cent);

    cudaFuncSetAttribute(assign_kernel,
                         cudaFuncAttributeMaxDynamicSharedMemorySize, SMEM_REQ);
    assign_kernel<<<BB / 128, 512, SMEM_REQ>>>(pts);

    refine_kernel<<<BB / 4, 128>>>(pts, cent, o_assign, o_dist, o_disp);

    scan_kernel<<<1, KK>>>(o_nn);

    label_kernel<<<BB / 8, 256>>>(labs, rl, o_dlab, o_displ);

    cluster_kernel<<<KK, 256>>>(pts, labs, o_nsum, o_nlab);
}